// round 9
// baseline (speedup 1.0000x reference)
#include <cuda_runtime.h>
#include <cuda_bf16.h>
#include <cstdint>

// World-model (confirmed by R7 pass, rel_err = 0.0):
//   d_in[0] = res  : float32 [M, N, D]  (harness serializes bf16 -> f32, exact)
//   d_in[1] = h_pre: float32 [M, N]
//   d_out   = out  : float32 [M, D]
// out[m,d] = f32( bf16_round( sum_n res[m,n,d] * h[m,n] ) ), fp32 accum.
//
// R7 measured: 186.3us, DRAM 91.5%, HBM 7251 GB/s (90.6% of spec), compute idle.
// R8 change: streaming cache hints (__ldcs / __stcs) — zero-reuse stream, so
// evict-first loads + streaming stores reduce L2 set contention between the
// 1 GiB read stream and the 256 MiB write stream.
static constexpr int M_DIM = 16384;
static constexpr int N_DIM = 4;
static constexpr int D_DIM = 4096;
static constexpr long long RES_ELEMS = (long long)M_DIM * N_DIM * D_DIM;

__global__ void __launch_bounds__(512)
mhc_wsum_f32_kernel(const float* __restrict__ res,
                    const float* __restrict__ h_pre,
                    float* __restrict__ out)
{
    const int m = blockIdx.x;
    const int t = threadIdx.x;              // 0..511
    const int d0 = t * 8;                   // 8 consecutive f32 per thread

    // Per-row weights (16 B, shared by the CTA — keep default caching, it's reused).
    const float4 w4 = *reinterpret_cast<const float4*>(h_pre + (size_t)m * N_DIM);
    const float w[4] = {w4.x, w4.y, w4.z, w4.w};

    const float* base = res + (size_t)m * N_DIM * D_DIM + d0;

    // Front-batch 8 independent 128-bit streaming loads (2 per stream).
    float4 v[N_DIM][2];
#pragma unroll
    for (int n = 0; n < N_DIM; ++n) {
        const float4* p = reinterpret_cast<const float4*>(base + (size_t)n * D_DIM);
        v[n][0] = __ldcs(p);
        v[n][1] = __ldcs(p + 1);
    }

    float acc[8] = {0,0,0,0,0,0,0,0};
#pragma unroll
    for (int n = 0; n < N_DIM; ++n) {
        const float wn = w[n];
        acc[0] = fmaf(v[n][0].x, wn, acc[0]);
        acc[1] = fmaf(v[n][0].y, wn, acc[1]);
        acc[2] = fmaf(v[n][0].z, wn, acc[2]);
        acc[3] = fmaf(v[n][0].w, wn, acc[3]);
        acc[4] = fmaf(v[n][1].x, wn, acc[4]);
        acc[5] = fmaf(v[n][1].y, wn, acc[5]);
        acc[6] = fmaf(v[n][1].z, wn, acc[6]);
        acc[7] = fmaf(v[n][1].w, wn, acc[7]);
    }

    // Round through bf16 (matches reference .astype(bfloat16)), widen to f32.
    float4 o0, o1;
    o0.x = __bfloat162float(__float2bfloat16_rn(acc[0]));
    o0.y = __bfloat162float(__float2bfloat16_rn(acc[1]));
    o0.z = __bfloat162float(__float2bfloat16_rn(acc[2]));
    o0.w = __bfloat162float(__float2bfloat16_rn(acc[3]));
    o1.x = __bfloat162float(__float2bfloat16_rn(acc[4]));
    o1.y = __bfloat162float(__float2bfloat16_rn(acc[5]));
    o1.z = __bfloat162float(__float2bfloat16_rn(acc[6]));
    o1.w = __bfloat162float(__float2bfloat16_rn(acc[7]));

    float4* o = reinterpret_cast<float4*>(out + (size_t)m * D_DIM + d0);
    __stcs(o,     o0);
    __stcs(o + 1, o1);
}

extern "C" void kernel_launch(void* const* d_in, const int* in_sizes, int n_in,
                              void* d_out, int out_size)
{
    const float* res;
    const float* h;
    if ((long long)in_sizes[0] == RES_ELEMS) {
        res = (const float*)d_in[0];
        h   = (const float*)d_in[1];
    } else {
        res = (const float*)d_in[1];
        h   = (const float*)d_in[0];
    }

    float* out = (float*)d_out;
    mhc_wsum_f32_kernel<<<M_DIM, 512>>>(res, h, out);
}